// round 10
// baseline (speedup 1.0000x reference)
#include <cuda_runtime.h>

#define NPTS   16384
#define NB     1024
#define YB     64
#define XMIN   (-5.0f)
#define INVW   ((float)NB / 10.0f)
#define SLAB   512
#define NSLAB  (NPTS / SLAB)              // 32
#define CELL   128
#define NCELL  (NPTS / CELL)              // 128
#define OFFSTRIDE 8                       // rc slots per query cell
#define PREPT  1024

typedef unsigned int u32;

// set 0 = predict, set 1 = target; pass p: queries = set p, refs = set 1-p
__device__ float4 g_pts[2][NPTS];         // x-slab then y-sorted (x,y,z, 0.5|p|^2)
__device__ u32    g_minbits[2][NPTS];
__device__ float4 g_ext[2][NCELL];        // per-cell (xmin, xmax, ymin, ymax)
__device__ float  g_cmax[2][NCELL];       // per query-cell max d2 after diag

__device__ __forceinline__ int bin_of(float x) {
    int b = (int)((x - XMIN) * INVW);
    return min(max(b, 0), NB - 1);
}
__device__ __forceinline__ u32 fflip(float f) {
    u32 u = __float_as_uint(f);
    return (u & 0x80000000u) ? ~u : (u | 0x80000000u);
}
__device__ __forceinline__ float funflip(u32 u) {
    u = (u & 0x80000000u) ? (u ^ 0x80000000u) : ~u;
    return __uint_as_float(u);
}

// ---------- K1: fused x-bin sort (validated R6/R8/R9) ----------
__global__ void __launch_bounds__(PREPT)
k_prep(const float* __restrict__ pr, const float* __restrict__ tg) {
    __shared__ int sh[NB];
    const int s = blockIdx.x;
    const int tid = threadIdx.x;
    const float* __restrict__ src = s ? tg : pr;

    sh[tid] = 0;
    __syncthreads();
#pragma unroll
    for (int k = 0; k < NPTS / PREPT; k++) {
        int i = tid + k * PREPT;
        atomicAdd(&sh[bin_of(src[3 * i])], 1);
    }
    __syncthreads();
    for (int d = 1; d < NB; d <<= 1) {
        int v = sh[tid];
        if (tid >= d) v += sh[tid - d];
        __syncthreads();
        sh[tid] = v;
        __syncthreads();
    }
    {
        int excl = (tid > 0) ? sh[tid - 1] : 0;
        __syncthreads();
        sh[tid] = excl;
    }
    __syncthreads();
#pragma unroll
    for (int k = 0; k < NPTS / PREPT; k++) {
        int i = tid + k * PREPT;
        float x = src[3 * i], y = src[3 * i + 1], z = src[3 * i + 2];
        int pos = atomicAdd(&sh[bin_of(x)], 1);
        g_pts[s][pos] = make_float4(x, y, z, 0.5f * (x * x + y * y + z * z));
        g_minbits[s][i] = 0xFFFFFFFFu;
    }
}

// ---------- K2: y-sort each 512-pt slab ----------
__global__ void __launch_bounds__(SLAB)
k_ysort() {
    __shared__ float4 buf[SLAB];
    __shared__ int hist[YB];
    __shared__ int cur[YB];
    const int slab = blockIdx.x, set = blockIdx.y, tid = threadIdx.x;
    const int base = slab * SLAB;

    float4 pt = g_pts[set][base + tid];
    if (tid < YB) hist[tid] = 0;
    __syncthreads();
    int yb = min(max((int)((pt.y - XMIN) * ((float)YB / 10.0f)), 0), YB - 1);
    atomicAdd(&hist[yb], 1);
    __syncthreads();
    if (tid == 0) {
        int acc = 0;
        for (int b = 0; b < YB; b++) { int v = hist[b]; cur[b] = acc; acc += v; }
    }
    __syncthreads();
    int pos = atomicAdd(&cur[yb], 1);
    buf[pos] = pt;
    __syncthreads();
    g_pts[set][base + tid] = buf[tid];
}

// ---------- K3: diagonal band — query cell vs 3 ref slabs ----------
__global__ void __launch_bounds__(CELL)
k_diag() {
    const int qc = blockIdx.x;
    const int sd = (int)blockIdx.y - 1;
    const int pass = blockIdx.z;
    const int rslab = (qc >> 2) + sd;
    if (rslab < 0 || rslab >= NSLAB) return;
    const int tid = threadIdx.x;

    __shared__ float4 sref[SLAB];
    const float4* __restrict__ refs = g_pts[1 - pass];
    {
        int rb = rslab * SLAB;
#pragma unroll
        for (int k = 0; k < SLAB / CELL; k++)
            sref[tid + k * CELL] = refs[rb + tid + k * CELL];
    }

    const int qp = qc * CELL + tid;
    const float4 q = g_pts[pass][qp];
    const float nx = -q.x, ny = -q.y, nz = -q.z;
    __syncthreads();

    const float INF = __int_as_float(0x7f800000);
    float m0 = INF, m1 = INF;
#pragma unroll 4
    for (int j = 0; j < SLAB; j += 2) {
        float4 t0 = sref[j];
        float4 t1 = sref[j + 1];
        float e;
        e = __fmaf_rn(nx, t0.x, t0.w); e = __fmaf_rn(ny, t0.y, e); e = __fmaf_rn(nz, t0.z, e);
        m0 = fminf(m0, e);
        e = __fmaf_rn(nx, t1.x, t1.w); e = __fmaf_rn(ny, t1.y, e); e = __fmaf_rn(nz, t1.z, e);
        m1 = fminf(m1, e);
    }
    atomicMin(&g_minbits[pass][qp], fflip(fminf(m0, m1)));
}

// ---------- K4: per-cell exact extents + cmax ----------
__global__ void __launch_bounds__(CELL)
k_bounds() {
    __shared__ float sxn[CELL], sxm[CELL], syn[CELL], sym[CELL], sd2[CELL];
    const int cell = blockIdx.x, set = blockIdx.y, tid = threadIdx.x;
    const int i = cell * CELL + tid;
    float4 q = g_pts[set][i];
    float m = funflip(g_minbits[set][i]);
    float d2 = fmaxf(2.0f * (m + q.w), 0.0f);
    sxn[tid] = q.x; sxm[tid] = q.x;
    syn[tid] = q.y; sym[tid] = q.y;
    sd2[tid] = d2;
    __syncthreads();
#pragma unroll
    for (int o = CELL / 2; o > 0; o >>= 1) {
        if (tid < o) {
            sxn[tid] = fminf(sxn[tid], sxn[tid + o]);
            sxm[tid] = fmaxf(sxm[tid], sxm[tid + o]);
            syn[tid] = fminf(syn[tid], syn[tid + o]);
            sym[tid] = fmaxf(sym[tid], sym[tid + o]);
            sd2[tid] = fmaxf(sd2[tid], sd2[tid + o]);
        }
        __syncthreads();
    }
    if (tid == 0) {
        g_ext[set][cell] = make_float4(sxn[0], sxm[0], syn[0], sym[0]);
        g_cmax[set][cell] = sd2[0];
    }
}

// ---------- K5: off-diagonal, rc-strided per block ----------
// grid (OFFSTRIDE, NCELL, 2), block CELL threads. Each block handles query
// cell qc and candidates rc = slot, slot+OFFSTRIDE, ... Skip test is
// block-uniform, so the barriers inside the live path are safe.
__global__ void __launch_bounds__(CELL)
k_off() {
    const int slot = blockIdx.x;
    const int qc = blockIdx.y;
    const int p = blockIdx.z;
    const int tid = threadIdx.x;

    const float4 eq = g_ext[p][qc];               // (xmin,xmax,ymin,ymax)
    const float cmax = g_cmax[p][qc];
    const int qslab = qc >> 2;

    const int qp = qc * CELL + tid;
    const float4 q = g_pts[p][qp];
    const float nx = -q.x, ny = -q.y, nz = -q.z;

    const float4* __restrict__ refs = g_pts[1 - p];
    __shared__ float4 sref[CELL];

    const float INF = __int_as_float(0x7f800000);
    float m0 = INF, m1 = INF;
    bool touched = false;

    for (int rc = slot; rc < NCELL; rc += OFFSTRIDE) {
        const int sd = (rc >> 2) - qslab;
        if (sd >= -1 && sd <= 1) continue;        // covered by k_diag (uniform)

        const float4 er = g_ext[1 - p][rc];
        float gx = fmaxf(fmaxf(er.x - eq.y, eq.x - er.y), 0.0f);
        float gy = fmaxf(fmaxf(er.z - eq.w, eq.z - er.w), 0.0f);
        if (gx * gx + gy * gy >= cmax) continue;  // uniform skip

        __syncthreads();                          // protect prior sref reads
        sref[tid] = refs[rc * CELL + tid];
        __syncthreads();

#pragma unroll 4
        for (int j = 0; j < CELL; j += 2) {
            float4 t0 = sref[j];
            float4 t1 = sref[j + 1];
            float e;
            e = __fmaf_rn(nx, t0.x, t0.w); e = __fmaf_rn(ny, t0.y, e); e = __fmaf_rn(nz, t0.z, e);
            m0 = fminf(m0, e);
            e = __fmaf_rn(nx, t1.x, t1.w); e = __fmaf_rn(ny, t1.y, e); e = __fmaf_rn(nz, t1.z, e);
            m1 = fminf(m1, e);
        }
        touched = true;
    }

    if (touched)
        atomicMin(&g_minbits[p][qp], fflip(fminf(m0, m1)));
}

// ---------- K6: deterministic reduction ----------
__global__ void __launch_bounds__(1024)
k_reduce(float* __restrict__ out) {
    __shared__ float sh[1024];
    float sum = 0.0f;
#pragma unroll
    for (int p = 0; p < 2; p++) {
        for (int i = threadIdx.x; i < NPTS; i += 1024) {
            float4 q = g_pts[p][i];
            float m = funflip(g_minbits[p][i]);
            sum += fmaxf(2.0f * (m + q.w), 0.0f);
        }
    }
    sh[threadIdx.x] = sum;
    __syncthreads();
#pragma unroll
    for (int o = 512; o > 0; o >>= 1) {
        if (threadIdx.x < o) sh[threadIdx.x] += sh[threadIdx.x + o];
        __syncthreads();
    }
    if (threadIdx.x == 0)
        out[0] = sh[0] * (1.0f / (float)NPTS);
}

extern "C" void kernel_launch(void* const* d_in, const int* in_sizes, int n_in,
                              void* d_out, int out_size) {
    const float* pr = (const float*)d_in[0];   // predict [1,16384,3]
    const float* tg = (const float*)d_in[1];   // target  [1,16384,3]
    float* out = (float*)d_out;

    k_prep<<<2, PREPT>>>(pr, tg);

    dim3 ygrid(NSLAB, 2);
    k_ysort<<<ygrid, SLAB>>>();

    dim3 dgrid(NCELL, 3, 2);
    k_diag<<<dgrid, CELL>>>();

    dim3 bgrid(NCELL, 2);
    k_bounds<<<bgrid, CELL>>>();

    dim3 ogrid(OFFSTRIDE, NCELL, 2);
    k_off<<<ogrid, CELL>>>();

    k_reduce<<<1, 1024>>>(out);
}

// round 11
// speedup vs baseline: 1.1856x; 1.1856x over previous
#include <cuda_runtime.h>

#define NPTS   16384
#define NB     1024
#define YB     64
#define XMIN   (-5.0f)
#define INVW   ((float)NB / 10.0f)
#define SLAB   512
#define NSLAB  (NPTS / SLAB)              // 32
#define CELL   128
#define NCELL  (NPTS / CELL)              // 128
#define PREPT  1024
#define OFFG   2048                       // persistent blocks for k_off
#define MAXWORK (2 * NCELL * NCELL)

typedef unsigned int u32;

// set 0 = predict, set 1 = target; pass p: queries = set p, refs = set 1-p
__device__ float4 g_pts[2][NPTS];         // x-slab then y-sorted (x,y,z, 0.5|p|^2)
__device__ u32    g_minbits[2][NPTS];
__device__ float4 g_ext[2][NCELL];        // per-cell (xmin, xmax, ymin, ymax)
__device__ float  g_cmax[2][NCELL];       // per query-cell max d2 after diag
__device__ int    g_nwork;
__device__ int    g_work[MAXWORK];        // packed: p<<15 | qc<<8 | rc (hi) -- see pack below

__device__ __forceinline__ int bin_of(float x) {
    int b = (int)((x - XMIN) * INVW);
    return min(max(b, 0), NB - 1);
}
__device__ __forceinline__ u32 fflip(float f) {
    u32 u = __float_as_uint(f);
    return (u & 0x80000000u) ? ~u : (u | 0x80000000u);
}
__device__ __forceinline__ float funflip(u32 u) {
    u = (u & 0x80000000u) ? (u ^ 0x80000000u) : ~u;
    return __uint_as_float(u);
}

// ---------- K1: fused x-bin sort (validated R6-R10) ----------
__global__ void __launch_bounds__(PREPT)
k_prep(const float* __restrict__ pr, const float* __restrict__ tg) {
    __shared__ int sh[NB];
    const int s = blockIdx.x;
    const int tid = threadIdx.x;
    const float* __restrict__ src = s ? tg : pr;

    if (s == 0 && tid == 0) g_nwork = 0;   // reset worklist counter each call

    sh[tid] = 0;
    __syncthreads();
#pragma unroll
    for (int k = 0; k < NPTS / PREPT; k++) {
        int i = tid + k * PREPT;
        atomicAdd(&sh[bin_of(src[3 * i])], 1);
    }
    __syncthreads();
    for (int d = 1; d < NB; d <<= 1) {
        int v = sh[tid];
        if (tid >= d) v += sh[tid - d];
        __syncthreads();
        sh[tid] = v;
        __syncthreads();
    }
    {
        int excl = (tid > 0) ? sh[tid - 1] : 0;
        __syncthreads();
        sh[tid] = excl;
    }
    __syncthreads();
#pragma unroll
    for (int k = 0; k < NPTS / PREPT; k++) {
        int i = tid + k * PREPT;
        float x = src[3 * i], y = src[3 * i + 1], z = src[3 * i + 2];
        int pos = atomicAdd(&sh[bin_of(x)], 1);
        g_pts[s][pos] = make_float4(x, y, z, 0.5f * (x * x + y * y + z * z));
        g_minbits[s][i] = 0xFFFFFFFFu;
    }
}

// ---------- K2: y-sort each 512-pt slab ----------
__global__ void __launch_bounds__(SLAB)
k_ysort() {
    __shared__ float4 buf[SLAB];
    __shared__ int hist[YB];
    __shared__ int cur[YB];
    const int slab = blockIdx.x, set = blockIdx.y, tid = threadIdx.x;
    const int base = slab * SLAB;

    float4 pt = g_pts[set][base + tid];
    if (tid < YB) hist[tid] = 0;
    __syncthreads();
    int yb = min(max((int)((pt.y - XMIN) * ((float)YB / 10.0f)), 0), YB - 1);
    atomicAdd(&hist[yb], 1);
    __syncthreads();
    if (tid == 0) {
        int acc = 0;
        for (int b = 0; b < YB; b++) { int v = hist[b]; cur[b] = acc; acc += v; }
    }
    __syncthreads();
    int pos = atomicAdd(&cur[yb], 1);
    buf[pos] = pt;
    __syncthreads();
    g_pts[set][base + tid] = buf[tid];
}

// ---------- K3: diagonal band — query cell vs 3 ref slabs ----------
__global__ void __launch_bounds__(CELL)
k_diag() {
    const int qc = blockIdx.x;
    const int sd = (int)blockIdx.y - 1;
    const int pass = blockIdx.z;
    const int rslab = (qc >> 2) + sd;
    if (rslab < 0 || rslab >= NSLAB) return;
    const int tid = threadIdx.x;

    __shared__ float4 sref[SLAB];
    const float4* __restrict__ refs = g_pts[1 - pass];
    {
        int rb = rslab * SLAB;
#pragma unroll
        for (int k = 0; k < SLAB / CELL; k++)
            sref[tid + k * CELL] = refs[rb + tid + k * CELL];
    }

    const int qp = qc * CELL + tid;
    const float4 q = g_pts[pass][qp];
    const float nx = -q.x, ny = -q.y, nz = -q.z;
    __syncthreads();

    const float INF = __int_as_float(0x7f800000);
    float m0 = INF, m1 = INF;
#pragma unroll 4
    for (int j = 0; j < SLAB; j += 2) {
        float4 t0 = sref[j];
        float4 t1 = sref[j + 1];
        float e;
        e = __fmaf_rn(nx, t0.x, t0.w); e = __fmaf_rn(ny, t0.y, e); e = __fmaf_rn(nz, t0.z, e);
        m0 = fminf(m0, e);
        e = __fmaf_rn(nx, t1.x, t1.w); e = __fmaf_rn(ny, t1.y, e); e = __fmaf_rn(nz, t1.z, e);
        m1 = fminf(m1, e);
    }
    atomicMin(&g_minbits[pass][qp], fflip(fminf(m0, m1)));
}

// ---------- K4: per-cell exact extents + cmax ----------
__global__ void __launch_bounds__(CELL)
k_bounds() {
    __shared__ float sxn[CELL], sxm[CELL], syn[CELL], sym[CELL], sd2[CELL];
    const int cell = blockIdx.x, set = blockIdx.y, tid = threadIdx.x;
    const int i = cell * CELL + tid;
    float4 q = g_pts[set][i];
    float m = funflip(g_minbits[set][i]);
    float d2 = fmaxf(2.0f * (m + q.w), 0.0f);
    sxn[tid] = q.x; sxm[tid] = q.x;
    syn[tid] = q.y; sym[tid] = q.y;
    sd2[tid] = d2;
    __syncthreads();
#pragma unroll
    for (int o = CELL / 2; o > 0; o >>= 1) {
        if (tid < o) {
            sxn[tid] = fminf(sxn[tid], sxn[tid + o]);
            sxm[tid] = fmaxf(sxm[tid], sxm[tid + o]);
            syn[tid] = fminf(syn[tid], syn[tid + o]);
            sym[tid] = fmaxf(sym[tid], sym[tid + o]);
            sd2[tid] = fmaxf(sd2[tid], sd2[tid + o]);
        }
        __syncthreads();
    }
    if (tid == 0) {
        g_ext[set][cell] = make_float4(sxn[0], sxm[0], syn[0], sym[0]);
        g_cmax[set][cell] = sd2[0];
    }
}

// ---------- K5: build compacted worklist of live (p, qc, rc) ----------
// grid (NCELL, 2), NCELL threads: thread rc tests pair (qc, rc) for pass p.
__global__ void __launch_bounds__(NCELL)
k_build() {
    const int qc = blockIdx.x, p = blockIdx.y, rc = threadIdx.x;
    const int sd = (rc >> 2) - (qc >> 2);
    if (sd >= -1 && sd <= 1) return;              // covered by k_diag

    const float4 eq = g_ext[p][qc];
    const float4 er = g_ext[1 - p][rc];
    float gx = fmaxf(fmaxf(er.x - eq.y, eq.x - er.y), 0.0f);
    float gy = fmaxf(fmaxf(er.z - eq.w, eq.z - er.w), 0.0f);
    if (gx * gx + gy * gy >= g_cmax[p][qc]) return;

    int w = atomicAdd(&g_nwork, 1);
    g_work[w] = (p << 15) | (qc << 8) | rc;       // qc,rc in [0,128), p in {0,1}
}

// ---------- K6: persistent off-diagonal over the worklist ----------
__global__ void __launch_bounds__(CELL)
k_off() {
    const int tid = threadIdx.x;
    const int n = g_nwork;                        // uniform across grid
    __shared__ float4 sref[CELL];
    const float INF = __int_as_float(0x7f800000);

    for (int w = blockIdx.x; w < n; w += OFFG) {
        const int e = g_work[w];                  // block-uniform
        const int p = e >> 15;
        const int qc = (e >> 8) & 0x7F;
        const int rc = e & 0xFF & 0x7F;

        sref[tid] = g_pts[1 - p][rc * CELL + tid];

        const int qp = qc * CELL + tid;
        const float4 q = g_pts[p][qp];
        const float nx = -q.x, ny = -q.y, nz = -q.z;
        __syncthreads();

        float m0 = INF, m1 = INF;
#pragma unroll 4
        for (int j = 0; j < CELL; j += 2) {
            float4 t0 = sref[j];
            float4 t1 = sref[j + 1];
            float ev;
            ev = __fmaf_rn(nx, t0.x, t0.w); ev = __fmaf_rn(ny, t0.y, ev); ev = __fmaf_rn(nz, t0.z, ev);
            m0 = fminf(m0, ev);
            ev = __fmaf_rn(nx, t1.x, t1.w); ev = __fmaf_rn(ny, t1.y, ev); ev = __fmaf_rn(nz, t1.z, ev);
            m1 = fminf(m1, ev);
        }
        atomicMin(&g_minbits[p][qp], fflip(fminf(m0, m1)));
        __syncthreads();                          // protect sref for next entry
    }
}

// ---------- K7: deterministic reduction ----------
__global__ void __launch_bounds__(1024)
k_reduce(float* __restrict__ out) {
    __shared__ float sh[1024];
    float sum = 0.0f;
#pragma unroll
    for (int p = 0; p < 2; p++) {
        for (int i = threadIdx.x; i < NPTS; i += 1024) {
            float4 q = g_pts[p][i];
            float m = funflip(g_minbits[p][i]);
            sum += fmaxf(2.0f * (m + q.w), 0.0f);
        }
    }
    sh[threadIdx.x] = sum;
    __syncthreads();
#pragma unroll
    for (int o = 512; o > 0; o >>= 1) {
        if (threadIdx.x < o) sh[threadIdx.x] += sh[threadIdx.x + o];
        __syncthreads();
    }
    if (threadIdx.x == 0)
        out[0] = sh[0] * (1.0f / (float)NPTS);
}

extern "C" void kernel_launch(void* const* d_in, const int* in_sizes, int n_in,
                              void* d_out, int out_size) {
    const float* pr = (const float*)d_in[0];   // predict [1,16384,3]
    const float* tg = (const float*)d_in[1];   // target  [1,16384,3]
    float* out = (float*)d_out;

    k_prep<<<2, PREPT>>>(pr, tg);

    dim3 ygrid(NSLAB, 2);
    k_ysort<<<ygrid, SLAB>>>();

    dim3 dgrid(NCELL, 3, 2);
    k_diag<<<dgrid, CELL>>>();

    dim3 bgrid(NCELL, 2);
    k_bounds<<<bgrid, CELL>>>();

    dim3 wgrid(NCELL, 2);
    k_build<<<wgrid, NCELL>>>();

    k_off<<<OFFG, CELL>>>();

    k_reduce<<<1, 1024>>>(out);
}